// round 3
// baseline (speedup 1.0000x reference)
#include <cuda_runtime.h>

#define HH 352
#define WW 352
#define NB 8

#define TILE 32
#define RR 5
#define HALO_W (TILE + 2*RR)     // 42 sites in x
#define PAIRROWS (TILE/2 + 2*RR) // 26 pair-rows
#define SITEB 48                 // bytes per site: A{r,r,g,g} B{b,b,E,E} C{s,s} +8 pad
#define ROWB 2176                // 48*42 + 16*10 = 2176 (swizzled row bytes)
#define SMEM_SZ (PAIRROWS * ROWB)
#define NTHREADS 128

typedef unsigned long long u64;
union F2U { float2 f; u64 u; };

__device__ __forceinline__ u64 pk2(float lo, float hi){ F2U t; t.f.x=lo; t.f.y=hi; return t.u; }
__device__ __forceinline__ float2 up2(u64 v){ F2U t; t.u=v; return t.f; }
__device__ __forceinline__ u64 fma2(u64 a,u64 b,u64 c){ u64 d; asm("fma.rn.f32x2 %0,%1,%2,%3;":"=l"(d):"l"(a),"l"(b),"l"(c)); return d; }
__device__ __forceinline__ u64 add2(u64 a,u64 b){ u64 d; asm("add.rn.f32x2 %0,%1,%2;":"=l"(d):"l"(a),"l"(b)); return d; }
__device__ __forceinline__ float ex2f(float x){ float r; asm("ex2.approx.ftz.f32 %0,%1;":"=f"(r):"f"(x)); return r; }

__device__ float g_num;
__device__ float g_den;

__global__ void init_kernel() { g_num = 0.0f; g_den = 0.0f; }

// swizzled byte offset of site x in a pair-row: 48B/site + 16B pad per 4-site group
__device__ __forceinline__ int soffx(int x){ return x * SITEB + ((x >> 2) << 4); }

#define KLOG 288.53900817779268f   // alpha * log2(e)
#define K2LOG 577.07801635558536f  // 2 * alpha * log2(e)

__global__ __launch_bounds__(NTHREADS) void loss_kernel(
    const float* __restrict__ pred,
    const float* __restrict__ feat)
{
    extern __shared__ unsigned char smem[];

    const int n  = blockIdx.z;
    const int x0 = blockIdx.x * TILE;
    const int y0 = blockIdx.y * TILE;
    const int tid = threadIdx.x;
    const int txb = (tid & 7) * 4;   // first of 4 consecutive x pixels
    const int p0  = tid >> 3;        // pair row 0..15 (rows y0+p0, y0+16+p0)

    const float* pr = pred + (size_t)n * (HH * WW);
    const float* fr = feat + (size_t)n * (3 * HH * WW);

    // ---- Fill halo tile. Site (p,x): pixels (y0+p-5, x0+x-5) [lo] and +16 rows [hi].
    //      A = {r_lo,r_hi,g_lo,g_hi}  B = {b_lo,b_hi,E_lo,E_hi}  C = {s_lo,s_hi}
    //      E = -K*(r^2+g^2+b^2), zero padding outside image.
    for (int i = tid; i < PAIRROWS * HALO_W; i += NTHREADS) {
        int p = i / HALO_W;
        int x = i - p * HALO_W;
        int gyL = y0 + p - RR;
        int gyH = gyL + 16;
        int gx  = x0 + x - RR;
        float rl=0.f,gl=0.f,bl=0.f,sl=0.f, rh=0.f,gh=0.f,bh=0.f,sh=0.f;
        bool inx = ((unsigned)gx < WW);
        if (inx && (unsigned)gyL < HH) {
            int idx = gyL * WW + gx;
            rl = fr[idx]; gl = fr[HH*WW + idx]; bl = fr[2*HH*WW + idx]; sl = pr[idx];
        }
        if (inx && (unsigned)gyH < HH) {
            int idx = gyH * WW + gx;
            rh = fr[idx]; gh = fr[HH*WW + idx]; bh = fr[2*HH*WW + idx]; sh = pr[idx];
        }
        float El = -KLOG * (rl*rl + gl*gl + bl*bl);
        float Eh = -KLOG * (rh*rh + gh*gh + bh*bh);
        unsigned char* dst = smem + p * ROWB + soffx(x);
        *(float4*)(dst)      = make_float4(rl, rh, gl, gh);
        *(float4*)(dst + 16) = make_float4(bl, bh, El, Eh);
        *(float2*)(dst + 32) = make_float2(sl, sh);
    }
    __syncthreads();

    // ---- Centers (4 pixels in x, each lo/hi pair): 2K-scaled channels, Ec, -s
    u64 cr2[4], cg2[4], cb2[4], Ec[4], csn[4];
    #pragma unroll
    for (int j = 0; j < 4; ++j) {
        const unsigned char* cp = smem + (p0 + RR) * ROWB + soffx(txb + RR + j);
        ulonglong2 A = *(const ulonglong2*)cp;
        ulonglong2 B = *(const ulonglong2*)(cp + 16);
        u64 S = *(const u64*)(cp + 32);
        float2 r2 = up2(A.x), g2 = up2(A.y), b2 = up2(B.x), s2 = up2(S);
        cr2[j] = pk2(K2LOG*r2.x, K2LOG*r2.y);
        cg2[j] = pk2(K2LOG*g2.x, K2LOG*g2.y);
        cb2[j] = pk2(K2LOG*b2.x, K2LOG*b2.y);
        Ec[j]  = B.y;
        csn[j] = pk2(-s2.x, -s2.y);
    }

    u64 loss2[4] = {0ull, 0ull, 0ull, 0ull};

    // ---- 11x11 bilateral accumulation: t = Ew + Ec + 2K*(w . c), w = ex2(t)
    #pragma unroll 1
    for (int dy = 0; dy < 2*RR + 1; ++dy) {
        const unsigned char* rb = smem + (p0 + dy) * ROWB + soffx(txb);
        #pragma unroll
        for (int s = 0; s < 14; ++s) {
            const unsigned char* sp = rb + s * SITEB + ((s >> 2) << 4);
            ulonglong2 A = *(const ulonglong2*)sp;
            ulonglong2 B = *(const ulonglong2*)(sp + 16);
            u64 ws = *(const u64*)(sp + 32);
            u64 wr = A.x, wg = A.y, wb = B.x, wE = B.y;
            #pragma unroll
            for (int j = 0; j < 4; ++j) {
                int dx = s - j;
                if (dx < 0 || dx > 10) continue;
                u64 t = add2(wE, Ec[j]);
                t = fma2(wb, cb2[j], t);
                t = fma2(wg, cg2[j], t);
                t = fma2(wr, cr2[j], t);
                float2 tf = up2(t);
                u64 w2 = pk2(ex2f(tf.x), ex2f(tf.y));
                u64 d  = add2(ws, csn[j]) & 0x7FFFFFFF7FFFFFFFull;
                loss2[j] = fma2(w2, d, loss2[j]);
            }
        }
    }

    // ---- Edge mask (5x5 dilate/erode over valid pixels) + masked accumulation
    float num = 0.0f, den = 0.0f;
    #pragma unroll 1
    for (int j = 0; j < 4; ++j) {
        bool anyL = false, allL = true, anyH = false, allH = true;
        #pragma unroll
        for (int dy2 = -2; dy2 <= 2; ++dy2) {
            #pragma unroll
            for (int dx2 = -2; dx2 <= 2; ++dx2) {
                int hp = p0 + RR + dy2;
                int hx = txb + RR + j + dx2;
                u64 spair = *(const u64*)(smem + hp * ROWB + soffx(hx) + 32);
                float2 sv = up2(spair);
                int gyL = y0 + p0 + dy2;
                int gyH = gyL + 16;
                int gx  = x0 + txb + j + dx2;
                bool inx  = ((unsigned)gx < WW);
                bool inbL = inx && ((unsigned)gyL < HH);
                bool inbH = inx && ((unsigned)gyH < HH);
                bool lL = sv.x > 0.5f;
                bool lH = sv.y > 0.5f;
                anyL = anyL || (inbL && lL);
                allL = allL && (!inbL || lL);
                anyH = anyH || (inbH && lH);
                allH = allH && (!inbH || lH);
            }
        }
        float mL = (anyL ? 1.0f : 0.0f) - (allL ? 1.0f : 0.0f);
        float mH = (anyH ? 1.0f : 0.0f) - (allH ? 1.0f : 0.0f);
        float2 lj = up2(loss2[j]);
        num += (mL != 0.0f ? lj.x : 0.0f) + (mH != 0.0f ? lj.y : 0.0f);
        den += mL + mH;
    }

    // ---- Block reduction + atomics
    #pragma unroll
    for (int o = 16; o > 0; o >>= 1) {
        num += __shfl_xor_sync(0xffffffffu, num, o);
        den += __shfl_xor_sync(0xffffffffu, den, o);
    }
    __shared__ float s_num[NTHREADS/32];
    __shared__ float s_den[NTHREADS/32];
    const int wid = tid >> 5;
    const int lid = tid & 31;
    if (lid == 0) { s_num[wid] = num; s_den[wid] = den; }
    __syncthreads();
    if (wid == 0) {
        float a = (lid < NTHREADS/32) ? s_num[lid] : 0.0f;
        float b = (lid < NTHREADS/32) ? s_den[lid] : 0.0f;
        #pragma unroll
        for (int o = 2; o > 0; o >>= 1) {
            a += __shfl_xor_sync(0xffffffffu, a, o);
            b += __shfl_xor_sync(0xffffffffu, b, o);
        }
        if (lid == 0) { atomicAdd(&g_num, a); atomicAdd(&g_den, b); }
    }
}

__global__ void final_kernel(float* __restrict__ out) {
    out[0] = g_num / (g_den + 1e-6f);
}

extern "C" void kernel_launch(void* const* d_in, const int* in_sizes, int n_in,
                              void* d_out, int out_size) {
    const float* pred = (const float*)d_in[0]; // (8,1,352,352)
    const float* feat = (const float*)d_in[1]; // (8,3,352,352)
    float* out = (float*)d_out;

    cudaFuncSetAttribute(loss_kernel, cudaFuncAttributeMaxDynamicSharedMemorySize, SMEM_SZ);

    init_kernel<<<1, 1>>>();
    dim3 grid(WW / TILE, HH / TILE, NB); // (11, 11, 8)
    loss_kernel<<<grid, NTHREADS, SMEM_SZ>>>(pred, feat);
    final_kernel<<<1, 1>>>(out);
}